// round 4
// baseline (speedup 1.0000x reference)
#include <cuda_runtime.h>

#define FULL_MASK 0xFFFFFFFFu

// ---- packed f32x2 helpers (sm_103a FFMA2/FMUL2 via PTX) ----
__device__ __forceinline__ unsigned long long pack2(float lo, float hi) {
    unsigned long long r;
    asm("mov.b64 %0, {%1, %2};" : "=l"(r) : "f"(lo), "f"(hi));
    return r;
}
__device__ __forceinline__ void unpack2(unsigned long long v, float& lo, float& hi) {
    asm("mov.b64 {%0, %1}, %2;" : "=f"(lo), "=f"(hi) : "l"(v));
}
__device__ __forceinline__ unsigned long long fma2(unsigned long long a,
                                                   unsigned long long b,
                                                   unsigned long long c) {
    unsigned long long r;
    asm("fma.rn.f32x2 %0, %1, %2, %3;" : "=l"(r) : "l"(a), "l"(b), "l"(c));
    return r;
}
__device__ __forceinline__ unsigned long long mul2(unsigned long long a,
                                                   unsigned long long b) {
    unsigned long long r;
    asm("mul.rn.f32x2 %0, %1, %2;" : "=l"(r) : "l"(a), "l"(b));
    return r;
}

// A 128-elem row's 4 per-lane floats, held as two packed f32x2.
struct Row { unsigned long long p0, p1; };  // (x,y), (z,w)

// In-register butterfly stages over index bits 0,1 (cross-component: scalar).
__device__ __forceinline__ Row stage12(float4 v) {
    float a = v.x + v.y, b = v.x - v.y;
    float c = v.z + v.w, d = v.z - v.w;
    Row r;
    r.p0 = pack2(a + c, b + d);
    r.p1 = pack2(a - c, b - d);
    return r;
}

// One cross-lane butterfly stage: v = fma(v, sgn, partner) where
// sgn = -1 for lanes with (lane & mask) set, +1 otherwise.
// Bit-exact with (o - v) / (v + o).
__device__ __forceinline__ void xstage(Row& r, unsigned long long sgn, int mask) {
    float x, y, z, w;
    unpack2(r.p0, x, y);
    unpack2(r.p1, z, w);
    float ox = __shfl_xor_sync(FULL_MASK, x, mask);
    float oy = __shfl_xor_sync(FULL_MASK, y, mask);
    float oz = __shfl_xor_sync(FULL_MASK, z, mask);
    float ow = __shfl_xor_sync(FULL_MASK, w, mask);
    r.p0 = fma2(r.p0, sgn, pack2(ox, oy));
    r.p1 = fma2(r.p1, sgn, pack2(oz, ow));
}

__device__ __forceinline__ void store_row(float4* __restrict__ p, long long idx, Row r) {
    float4 v;
    unpack2(r.p0, v.x, v.y);
    unpack2(r.p1, v.z, v.w);
    p[idx] = v;
}

// 4-bit symmetric fake-quant of a rotated+scaled k row, then store.
__device__ __forceinline__ void quant_store(float4* __restrict__ p, long long idx, Row r) {
    float x, y, z, w;
    unpack2(r.p0, x, y);
    unpack2(r.p1, z, w);
    float amax = fmaxf(fmaxf(fabsf(x), fabsf(y)), fmaxf(fabsf(z), fabsf(w)));
#pragma unroll
    for (int m = 16; m >= 1; m >>= 1)
        amax = fmaxf(amax, __shfl_xor_sync(FULL_MASK, amax, m));
    if (amax == 0.0f) amax = 1.0f;
    const float qscale = amax / 7.0f;      // single rounding, matches reference
    const float qinv = 1.0f / qscale;      // one correctly-rounded div per row
    float4 v;
    v.x = fminf(fmaxf(rintf(x * qinv), -8.0f), 7.0f) * qscale;
    v.y = fminf(fmaxf(rintf(y * qinv), -8.0f), 7.0f) * qscale;
    v.z = fminf(fmaxf(rintf(z * qinv), -8.0f), 7.0f) * qscale;
    v.w = fminf(fmaxf(rintf(w * qinv), -8.0f), 7.0f) * qscale;
    p[idx] = v;
}

// One warp handles FOUR row-indices: 4 q rows + 4 k rows.
// 8 independent float4 loads issued up front (MLP=8/thread); the 8 FWHT
// shfl chains interleave to hide SHFL + memory latency.
__global__ void __launch_bounds__(256)
qk_rot_quant_kernel(const float4* __restrict__ qin,
                    const float4* __restrict__ kin,
                    float4* __restrict__ qout,
                    float4* __restrict__ kout,
                    int ngroups) {
    const int gwarp = (blockIdx.x * blockDim.x + threadIdx.x) >> 5;
    const int lane = threadIdx.x & 31;
    if (gwarp >= ngroups) return;

    const float s = 0.088388347648318447f;  // 1/sqrt(128)
    const unsigned long long s2 = pack2(s, s);

    const long long base = (long long)gwarp * 128 + lane;  // 4 rows * 32 f4/row

    // ---- issue all 8 loads before any compute ----
    float4 q0 = qin[base];
    float4 q1 = qin[base + 32];
    float4 q2 = qin[base + 64];
    float4 q3 = qin[base + 96];
    float4 k0 = kin[base];
    float4 k1 = kin[base + 32];
    float4 k2 = kin[base + 64];
    float4 k3 = kin[base + 96];

    // ---- Q: rotate (4 interleaved chains), scale, store ----
    {
        Row Q0 = stage12(q0), Q1 = stage12(q1), Q2 = stage12(q2), Q3 = stage12(q3);
#pragma unroll
        for (int i = 0; i < 5; i++) {
            const int m = 1 << i;
            const float sg = (lane & m) ? -1.0f : 1.0f;
            const unsigned long long sgn = pack2(sg, sg);
            xstage(Q0, sgn, m);
            xstage(Q1, sgn, m);
            xstage(Q2, sgn, m);
            xstage(Q3, sgn, m);
        }
        Q0.p0 = mul2(Q0.p0, s2); Q0.p1 = mul2(Q0.p1, s2);
        Q1.p0 = mul2(Q1.p0, s2); Q1.p1 = mul2(Q1.p1, s2);
        Q2.p0 = mul2(Q2.p0, s2); Q2.p1 = mul2(Q2.p1, s2);
        Q3.p0 = mul2(Q3.p0, s2); Q3.p1 = mul2(Q3.p1, s2);
        store_row(qout, base, Q0);
        store_row(qout, base + 32, Q1);
        store_row(qout, base + 64, Q2);
        store_row(qout, base + 96, Q3);
    }

    // ---- K: rotate, scale, quantize, store ----
    {
        Row K0 = stage12(k0), K1 = stage12(k1), K2 = stage12(k2), K3 = stage12(k3);
#pragma unroll
        for (int i = 0; i < 5; i++) {
            const int m = 1 << i;
            const float sg = (lane & m) ? -1.0f : 1.0f;
            const unsigned long long sgn = pack2(sg, sg);
            xstage(K0, sgn, m);
            xstage(K1, sgn, m);
            xstage(K2, sgn, m);
            xstage(K3, sgn, m);
        }
        K0.p0 = mul2(K0.p0, s2); K0.p1 = mul2(K0.p1, s2);
        K1.p0 = mul2(K1.p0, s2); K1.p1 = mul2(K1.p1, s2);
        K2.p0 = mul2(K2.p0, s2); K2.p1 = mul2(K2.p1, s2);
        K3.p0 = mul2(K3.p0, s2); K3.p1 = mul2(K3.p1, s2);
        quant_store(kout, base, K0);
        quant_store(kout, base + 32, K1);
        quant_store(kout, base + 64, K2);
        quant_store(kout, base + 96, K3);
    }
}

extern "C" void kernel_launch(void* const* d_in, const int* in_sizes, int n_in,
                              void* d_out, int out_size) {
    const float4* qin = (const float4*)d_in[0];
    const float4* kin = (const float4*)d_in[1];

    const int n_elems = in_sizes[0];     // 33554432
    const int nrows = n_elems / 128;     // 262144
    const int ngroups = nrows / 4;       // 65536 (4 rows per warp)

    float4* qout = (float4*)d_out;
    float4* kout = (float4*)d_out + (size_t)n_elems / 4;

    const int threads = 256;             // 8 warps = 32 rows per block
    const int groups_per_block = threads / 32;
    const int blocks = (ngroups + groups_per_block - 1) / groups_per_block;

    qk_rot_quant_kernel<<<blocks, threads>>>(qin, kin, qout, kout, ngroups);
}

// round 5
// speedup vs baseline: 1.0125x; 1.0125x over previous
#include <cuda_runtime.h>

#define FULL_MASK 0xFFFFFFFFu

// ---- packed f32x2 helpers (sm_103a FFMA2/FMUL2 via PTX) ----
__device__ __forceinline__ unsigned long long pack2(float lo, float hi) {
    unsigned long long r;
    asm("mov.b64 %0, {%1, %2};" : "=l"(r) : "f"(lo), "f"(hi));
    return r;
}
__device__ __forceinline__ void unpack2(unsigned long long v, float& lo, float& hi) {
    asm("mov.b64 {%0, %1}, %2;" : "=f"(lo), "=f"(hi) : "l"(v));
}
__device__ __forceinline__ unsigned long long fma2(unsigned long long a,
                                                   unsigned long long b,
                                                   unsigned long long c) {
    unsigned long long r;
    asm("fma.rn.f32x2 %0, %1, %2, %3;" : "=l"(r) : "l"(a), "l"(b), "l"(c));
    return r;
}
__device__ __forceinline__ unsigned long long mul2(unsigned long long a,
                                                   unsigned long long b) {
    unsigned long long r;
    asm("mul.rn.f32x2 %0, %1, %2;" : "=l"(r) : "l"(a), "l"(b));
    return r;
}

// A 128-elem row's 4 per-lane floats, held as two packed f32x2.
struct Row { unsigned long long p0, p1; };  // (x,y), (z,w)

// In-register butterfly stages over index bits 0,1.
__device__ __forceinline__ Row stage12(float4 v) {
    float a = v.x + v.y, b = v.x - v.y;
    float c = v.z + v.w, d = v.z - v.w;
    Row r;
    r.p0 = pack2(a + c, b + d);
    r.p1 = pack2(a - c, b - d);
    return r;
}

// One cross-lane butterfly stage: v = fma(v, sgn, partner).
// sgn = -1 where (lane & mask), else +1. Bit-exact with (o-v)/(v+o).
__device__ __forceinline__ void xstage(Row& r, unsigned long long sgn, int mask) {
    float x, y, z, w;
    unpack2(r.p0, x, y);
    unpack2(r.p1, z, w);
    float ox = __shfl_xor_sync(FULL_MASK, x, mask);
    float oy = __shfl_xor_sync(FULL_MASK, y, mask);
    float oz = __shfl_xor_sync(FULL_MASK, z, mask);
    float ow = __shfl_xor_sync(FULL_MASK, w, mask);
    r.p0 = fma2(r.p0, sgn, pack2(ox, oy));
    r.p1 = fma2(r.p1, sgn, pack2(oz, ow));
}

__device__ __forceinline__ float4 row_to_f4(Row r) {
    float4 v;
    unpack2(r.p0, v.x, v.y);
    unpack2(r.p1, v.z, v.w);
    return v;
}

// 4-bit symmetric fake-quant of a rotated+scaled k row; streaming store.
__device__ __forceinline__ void quant_store(float4* __restrict__ p, long long idx, Row r) {
    float x, y, z, w;
    unpack2(r.p0, x, y);
    unpack2(r.p1, z, w);
    float amax = fmaxf(fmaxf(fabsf(x), fabsf(y)), fmaxf(fabsf(z), fabsf(w)));
#pragma unroll
    for (int m = 16; m >= 1; m >>= 1)
        amax = fmaxf(amax, __shfl_xor_sync(FULL_MASK, amax, m));
    if (amax == 0.0f) amax = 1.0f;
    const float qscale = amax / 7.0f;   // single rounding, matches reference
    const float qinv = 1.0f / qscale;
    float4 v;
    v.x = fminf(fmaxf(rintf(x * qinv), -8.0f), 7.0f) * qscale;
    v.y = fminf(fmaxf(rintf(y * qinv), -8.0f), 7.0f) * qscale;
    v.z = fminf(fmaxf(rintf(z * qinv), -8.0f), 7.0f) * qscale;
    v.w = fminf(fmaxf(rintf(w * qinv), -8.0f), 7.0f) * qscale;
    __stcs(p + idx, v);
}

// One warp handles FOUR row-indices: 4 q rows + 4 k rows.
// All 8 loads streamed (.cs evict-first) and issued up-front; Q stores are
// issued before the K butterfly chains so the write burst overlaps compute.
__global__ void __launch_bounds__(256)
qk_rot_quant_kernel(const float4* __restrict__ qin,
                    const float4* __restrict__ kin,
                    float4* __restrict__ qout,
                    float4* __restrict__ kout,
                    int ngroups) {
    const int gwarp = (blockIdx.x * blockDim.x + threadIdx.x) >> 5;
    const int lane = threadIdx.x & 31;
    if (gwarp >= ngroups) return;

    const float s = 0.088388347648318447f;  // 1/sqrt(128)
    const unsigned long long s2 = pack2(s, s);

    const long long base = (long long)gwarp * 128 + lane;

    // ---- issue all 8 streaming loads before any compute (MLP=8) ----
    float4 q0 = __ldcs(qin + base);
    float4 q1 = __ldcs(qin + base + 32);
    float4 q2 = __ldcs(qin + base + 64);
    float4 q3 = __ldcs(qin + base + 96);
    float4 k0 = __ldcs(kin + base);
    float4 k1 = __ldcs(kin + base + 32);
    float4 k2 = __ldcs(kin + base + 64);
    float4 k3 = __ldcs(kin + base + 96);

    // ---- Q: rotate (4 interleaved chains), scale ----
    Row Q0 = stage12(q0), Q1 = stage12(q1), Q2 = stage12(q2), Q3 = stage12(q3);
#pragma unroll
    for (int i = 0; i < 5; i++) {
        const int m = 1 << i;
        const float sg = (lane & m) ? -1.0f : 1.0f;
        const unsigned long long sgn = pack2(sg, sg);
        xstage(Q0, sgn, m);
        xstage(Q1, sgn, m);
        xstage(Q2, sgn, m);
        xstage(Q3, sgn, m);
    }
    Q0.p0 = mul2(Q0.p0, s2); Q0.p1 = mul2(Q0.p1, s2);
    Q1.p0 = mul2(Q1.p0, s2); Q1.p1 = mul2(Q1.p1, s2);
    Q2.p0 = mul2(Q2.p0, s2); Q2.p1 = mul2(Q2.p1, s2);
    Q3.p0 = mul2(Q3.p0, s2); Q3.p1 = mul2(Q3.p1, s2);

    // ---- Q streaming stores (overlap with K chains below) ----
    __stcs(qout + base,      row_to_f4(Q0));
    __stcs(qout + base + 32, row_to_f4(Q1));
    __stcs(qout + base + 64, row_to_f4(Q2));
    __stcs(qout + base + 96, row_to_f4(Q3));

    // ---- K: rotate, scale, quantize, store ----
    Row K0 = stage12(k0), K1 = stage12(k1), K2 = stage12(k2), K3 = stage12(k3);
#pragma unroll
    for (int i = 0; i < 5; i++) {
        const int m = 1 << i;
        const float sg = (lane & m) ? -1.0f : 1.0f;
        const unsigned long long sgn = pack2(sg, sg);
        xstage(K0, sgn, m);
        xstage(K1, sgn, m);
        xstage(K2, sgn, m);
        xstage(K3, sgn, m);
    }
    K0.p0 = mul2(K0.p0, s2); K0.p1 = mul2(K0.p1, s2);
    K1.p0 = mul2(K1.p0, s2); K1.p1 = mul2(K1.p1, s2);
    K2.p0 = mul2(K2.p0, s2); K2.p1 = mul2(K2.p1, s2);
    K3.p0 = mul2(K3.p0, s2); K3.p1 = mul2(K3.p1, s2);

    quant_store(kout, base,      K0);
    quant_store(kout, base + 32, K1);
    quant_store(kout, base + 64, K2);
    quant_store(kout, base + 96, K3);
}

extern "C" void kernel_launch(void* const* d_in, const int* in_sizes, int n_in,
                              void* d_out, int out_size) {
    const float4* qin = (const float4*)d_in[0];
    const float4* kin = (const float4*)d_in[1];

    const int n_elems = in_sizes[0];   // 33554432
    const int nrows = n_elems / 128;   // 262144
    const int ngroups = nrows / 4;     // 65536

    float4* qout = (float4*)d_out;
    float4* kout = (float4*)d_out + (size_t)n_elems / 4;

    const int threads = 256;           // 8 warps = 32 rows per block
    const int groups_per_block = threads / 32;
    const int blocks = (ngroups + groups_per_block - 1) / groups_per_block;

    qk_rot_quant_kernel<<<blocks, threads>>>(qin, kin, qout, kout, ngroups);
}